// round 1
// baseline (speedup 1.0000x reference)
#include <cuda_runtime.h>

// Problem constants
#define NB 4
#define NS 2048
#define ND 1024
#define NH 16
#define NDK 64
#define NM (NB * NS)   // 8192 rows

// Scratch (device globals: allocation-free, allowed by harness rules)
__device__ float g_Q[NB * NH * NS * NDK];   // [B,H,S,dk]
__device__ float g_K[NB * NH * NS * NDK];
__device__ float g_V[NB * NH * NS * NDK];
__device__ float g_AO[NB * NS * ND];        // attention output, [B,S,D]

// ---------------------------------------------------------------------------
// NT GEMM: C[m,n] = sum_k A[m,k] * W[n,k] + bias[n]
//   A: [M=8192, K=1024] row-major, W: [N=1024, K=1024] row-major.
// mode 0: A = g_AO, C = Cp, row-major [M, N]   (output projection)
// mode 1/2/3: A = Ap, C = g_Q/g_K/g_V in heads layout [B,H,S,dk]
// Tile 128x128x16, 256 threads, 8x8 per thread.
// ---------------------------------------------------------------------------
__global__ __launch_bounds__(256) void sgemm_nt(
    const float* __restrict__ Ap, const float* __restrict__ W,
    const float* __restrict__ bias, float* __restrict__ Cp, int mode)
{
    const float* __restrict__ A = (mode == 0) ? (const float*)g_AO : Ap;

    __shared__ __align__(16) float As[16][128];
    __shared__ __align__(16) float Ws[16][128];

    const int tid = threadIdx.x;
    const int bm = blockIdx.y * 128;
    const int bn = blockIdx.x * 128;
    const int ty = tid >> 4;
    const int tx = tid & 15;

    float acc[8][8];
#pragma unroll
    for (int i = 0; i < 8; i++)
#pragma unroll
        for (int j = 0; j < 8; j++) acc[i][j] = 0.f;

    for (int k0 = 0; k0 < ND; k0 += 16) {
#pragma unroll
        for (int u = 0; u < 2; u++) {
            int idx = tid + u * 256;
            int r = idx >> 2;
            int q = idx & 3;
            float4 a = *(const float4*)(A + (bm + r) * ND + k0 + q * 4);
            As[q * 4 + 0][r] = a.x;
            As[q * 4 + 1][r] = a.y;
            As[q * 4 + 2][r] = a.z;
            As[q * 4 + 3][r] = a.w;
            float4 w = *(const float4*)(W + (bn + r) * ND + k0 + q * 4);
            Ws[q * 4 + 0][r] = w.x;
            Ws[q * 4 + 1][r] = w.y;
            Ws[q * 4 + 2][r] = w.z;
            Ws[q * 4 + 3][r] = w.w;
        }
        __syncthreads();
#pragma unroll
        for (int kk = 0; kk < 16; kk++) {
            float a[8], b[8];
            *(float4*)&a[0] = *(const float4*)&As[kk][ty * 8];
            *(float4*)&a[4] = *(const float4*)&As[kk][ty * 8 + 4];
            *(float4*)&b[0] = *(const float4*)&Ws[kk][tx * 8];
            *(float4*)&b[4] = *(const float4*)&Ws[kk][tx * 8 + 4];
#pragma unroll
            for (int i = 0; i < 8; i++)
#pragma unroll
                for (int j = 0; j < 8; j++)
                    acc[i][j] = fmaf(a[i], b[j], acc[i][j]);
        }
        __syncthreads();
    }

    float* C0 = (mode == 0) ? Cp
               : (mode == 1 ? (float*)g_Q : (mode == 2 ? (float*)g_K : (float*)g_V));

#pragma unroll
    for (int i = 0; i < 8; i++) {
        int m = bm + ty * 8 + i;
#pragma unroll
        for (int j = 0; j < 8; j += 4) {
            int n = bn + tx * 8 + j;
            float4 o;
            o.x = acc[i][j + 0] + bias[n + 0];
            o.y = acc[i][j + 1] + bias[n + 1];
            o.z = acc[i][j + 2] + bias[n + 2];
            o.w = acc[i][j + 3] + bias[n + 3];
            if (mode == 0) {
                *(float4*)(C0 + m * ND + n) = o;
            } else {
                int bb = m >> 11, s = m & 2047;   // m = b*2048 + s
                int hh = n >> 6, d = n & 63;      // n = h*64 + d
                *(float4*)(C0 + (((bb * NH + hh) * NS + s) * NDK) + d) = o;
            }
        }
    }
}

// ---------------------------------------------------------------------------
// Flash attention, fp32. One block = (b, h, 64-row q tile). 256 threads.
// Streams 64-col KV tiles; online softmax; P@V accumulated in registers.
// Smem: Qt [dk][64], KP [dk][64] (K transposed, later reused as P transposed),
//       Vs [64][dk]. 3 * 16 KB = 48 KB exactly (static-shared limit).
// ---------------------------------------------------------------------------
__global__ __launch_bounds__(256) void flash_attn(const int* __restrict__ mask)
{
    __shared__ __align__(16) float Qt[64 * 64];  // Qt[d][r]
    __shared__ __align__(16) float KP[64 * 64];  // Kt[d][c] -> Pt[c][r]
    __shared__ __align__(16) float Vs[64 * 64];  // Vs[j][d]

    const int tid = threadIdx.x;
    const int qt = blockIdx.x;
    const int h  = blockIdx.y;
    const int b  = blockIdx.z;
    const int ty = tid >> 4;
    const int tx = tid & 15;

    const float* Qb = g_Q + ((b * NH + h) * NS + qt * 64) * NDK;
    const float* Kb = g_K + ((b * NH + h) * NS) * NDK;
    const float* Vb = g_V + ((b * NH + h) * NS) * NDK;

    // Load Q tile transposed (r-major mapping: conflict-free smem stores)
#pragma unroll
    for (int u = 0; u < 4; u++) {
        int idx = tid + u * 256;
        int r = idx & 63;
        int q = idx >> 6;
        float4 a = *(const float4*)(Qb + r * NDK + q * 4);
        Qt[(q * 4 + 0) * 64 + r] = a.x;
        Qt[(q * 4 + 1) * 64 + r] = a.y;
        Qt[(q * 4 + 2) * 64 + r] = a.z;
        Qt[(q * 4 + 3) * 64 + r] = a.w;
    }

    const float NEG = __int_as_float(0xff800000);  // -inf
    float m_i[4] = {NEG, NEG, NEG, NEG};
    float l_i[4] = {0.f, 0.f, 0.f, 0.f};
    float acc[4][4];
#pragma unroll
    for (int i = 0; i < 4; i++)
#pragma unroll
        for (int j = 0; j < 4; j++) acc[i][j] = 0.f;

    const int qg0 = qt * 64 + ty * 4;

    for (int kt = 0; kt < NS / 64; kt++) {
        // K tile transposed into KP (r-major, conflict-free stores)
#pragma unroll
        for (int u = 0; u < 4; u++) {
            int idx = tid + u * 256;
            int r = idx & 63;
            int q = idx >> 6;
            float4 k4 = *(const float4*)(Kb + (kt * 64 + r) * NDK + q * 4);
            KP[(q * 4 + 0) * 64 + r] = k4.x;
            KP[(q * 4 + 1) * 64 + r] = k4.y;
            KP[(q * 4 + 2) * 64 + r] = k4.z;
            KP[(q * 4 + 3) * 64 + r] = k4.w;
        }
        // V tile direct copy (q-major: coalesced + conflict-free float4)
#pragma unroll
        for (int u = 0; u < 4; u++) {
            int idx = tid + u * 256;
            int r = idx >> 4;
            int q = idx & 15;
            *(float4*)&Vs[r * 64 + q * 4] =
                *(const float4*)(Vb + (kt * 64 + r) * NDK + q * 4);
        }
        __syncthreads();

        // scores: s[i][j] = sum_d Qt[d][ty*4+i] * Kt[d][tx*4+j]
        float s[4][4];
#pragma unroll
        for (int i = 0; i < 4; i++)
#pragma unroll
            for (int j = 0; j < 4; j++) s[i][j] = 0.f;

#pragma unroll 8
        for (int d = 0; d < 64; d++) {
            float4 a4 = *(const float4*)&Qt[d * 64 + ty * 4];
            float4 b4 = *(const float4*)&KP[d * 64 + tx * 4];
            float av[4] = {a4.x, a4.y, a4.z, a4.w};
            float bv[4] = {b4.x, b4.y, b4.z, b4.w};
#pragma unroll
            for (int i = 0; i < 4; i++)
#pragma unroll
                for (int j = 0; j < 4; j++)
                    s[i][j] = fmaf(av[i], bv[j], s[i][j]);
        }

        // mask + scale + online softmax update
        const int kg0 = kt * 64 + tx * 4;
        float p[4][4];
#pragma unroll
        for (int i = 0; i < 4; i++) {
            int4 mr = *(const int4*)(mask + (qg0 + i) * NS + kg0);
            s[i][0] = mr.x ? s[i][0] * 0.125f : -1e9f;
            s[i][1] = mr.y ? s[i][1] * 0.125f : -1e9f;
            s[i][2] = mr.z ? s[i][2] * 0.125f : -1e9f;
            s[i][3] = mr.w ? s[i][3] * 0.125f : -1e9f;

            float r = fmaxf(fmaxf(s[i][0], s[i][1]), fmaxf(s[i][2], s[i][3]));
            r = fmaxf(r, __shfl_xor_sync(0xffffffffu, r, 1));
            r = fmaxf(r, __shfl_xor_sync(0xffffffffu, r, 2));
            r = fmaxf(r, __shfl_xor_sync(0xffffffffu, r, 4));
            r = fmaxf(r, __shfl_xor_sync(0xffffffffu, r, 8));
            float mn = fmaxf(m_i[i], r);
            float corr = __expf(m_i[i] - mn);

            float rs = 0.f;
#pragma unroll
            for (int j = 0; j < 4; j++) {
                p[i][j] = __expf(s[i][j] - mn);
                rs += p[i][j];
            }
            rs += __shfl_xor_sync(0xffffffffu, rs, 1);
            rs += __shfl_xor_sync(0xffffffffu, rs, 2);
            rs += __shfl_xor_sync(0xffffffffu, rs, 4);
            rs += __shfl_xor_sync(0xffffffffu, rs, 8);

            l_i[i] = l_i[i] * corr + rs;
            m_i[i] = mn;
#pragma unroll
            for (int j = 0; j < 4; j++) acc[i][j] *= corr;
        }
        __syncthreads();  // everyone done reading Kt before overwriting with Pt

        // store P transposed: Pt[c][r]
#pragma unroll
        for (int j = 0; j < 4; j++)
            *(float4*)&KP[(tx * 4 + j) * 64 + ty * 4] =
                make_float4(p[0][j], p[1][j], p[2][j], p[3][j]);
        __syncthreads();

        // acc[i][jd] += sum_jj Pt[jj][ty*4+i] * Vs[jj][tx*4+jd]
#pragma unroll 8
        for (int jj = 0; jj < 64; jj++) {
            float4 p4 = *(const float4*)&KP[jj * 64 + ty * 4];
            float4 v4 = *(const float4*)&Vs[jj * 64 + tx * 4];
            float pa[4] = {p4.x, p4.y, p4.z, p4.w};
            float vb[4] = {v4.x, v4.y, v4.z, v4.w};
#pragma unroll
            for (int i = 0; i < 4; i++)
#pragma unroll
                for (int j = 0; j < 4; j++)
                    acc[i][j] = fmaf(pa[i], vb[j], acc[i][j]);
        }
        __syncthreads();  // before next tile overwrites KP / Vs
    }

    // epilogue: AO[b][s][h*64 + d] = acc / l
    float* Ob = g_AO + (b * NS) * ND + h * NDK;
#pragma unroll
    for (int i = 0; i < 4; i++) {
        float inv = 1.f / l_i[i];
        float4 o = make_float4(acc[i][0] * inv, acc[i][1] * inv,
                               acc[i][2] * inv, acc[i][3] * inv);
        *(float4*)(Ob + (qg0 + i) * ND + tx * 4) = o;
    }
}

// ---------------------------------------------------------------------------
extern "C" void kernel_launch(void* const* d_in, const int* in_sizes, int n_in,
                              void* d_out, int out_size)
{
    const float* q    = (const float*)d_in[0];
    const float* k    = (const float*)d_in[1];
    const float* v    = (const float*)d_in[2];
    const int*   mask = (const int*)d_in[3];
    const float* w_q  = (const float*)d_in[4];
    const float* b_q  = (const float*)d_in[5];
    const float* w_k  = (const float*)d_in[6];
    const float* b_k  = (const float*)d_in[7];
    const float* w_v  = (const float*)d_in[8];
    const float* b_v  = (const float*)d_in[9];
    const float* w_o  = (const float*)d_in[10];
    const float* b_o  = (const float*)d_in[11];

    dim3 ggrid(ND / 128, NM / 128);  // (8, 64)

    // Q/K/V projections -> heads layout scratch
    sgemm_nt<<<ggrid, 256>>>(q, w_q, b_q, nullptr, 1);
    sgemm_nt<<<ggrid, 256>>>(k, w_k, b_k, nullptr, 2);
    sgemm_nt<<<ggrid, 256>>>(v, w_v, b_v, nullptr, 3);

    // attention
    dim3 agrid(NS / 64, NH, NB);     // (32, 16, 4)
    flash_attn<<<agrid, 256>>>(mask);

    // output projection -> d_out
    sgemm_nt<<<ggrid, 256>>>(nullptr, w_o, b_o, (float*)d_out, 0);
}